// round 1
// baseline (speedup 1.0000x reference)
#include <cuda_runtime.h>

// BWSGODE: 8192-step serial scalar ODE.
// One thread runs the recurrence in registers with strict (unfused) IEEE fp32
// matching the JAX reference op-for-op; each step's 4-float state goes to
// shared memory via a single 128-bit STS. Afterwards the whole block fans the
// trajectory out to the (num_steps, 5) global layout (col 4 = i) in parallel.

__global__ void __launch_bounds__(256, 1)
bwsg_ode_kernel(const float* __restrict__ y0,
                const float* __restrict__ p,
                float* __restrict__ out,
                int num_steps) {
    extern __shared__ float4 traj[];  // num_steps entries (128 KB @ 8192)

    if (threadIdx.x == 0) {
        float B = y0[0];
        float W = y0[1];
        float S = y0[2];
        float G = y0[3];
        const float iv = y0[4];

        const float p0 = p[0], p1 = p[1], p2 = p[2], p3 = p[3], p4 = p[4];
        const float p5 = p[5], p6 = p[6], p7 = p[7], p8 = p[8], p9 = p[9];

        // interventional = (i != 0) as float; 1 - interventional
        const float fi = (iv != 0.0f) ? 1.0f : 0.0f;
        const float om = __fsub_rn(1.0f, fi);
        // threshold 5.0 + i - 1.0, replicated op-for-op
        const float thr = __fsub_rn(__fadd_rn(5.0f, iv), 1.0f);

        traj[0] = make_float4(B, W, S, G);

        float jf = 1.0f;
        for (int j = 1; j < num_steps; ++j) {
            // mask = interventional * (j >= thr) + (1 - interventional)
            // All factors are exactly 0.0f/1.0f, so this is exact.
            const float ge   = (jf >= thr) ? 1.0f : 0.0f;
            const float mask = __fadd_rn(__fmul_rn(fi, ge), om);
            // mask in {0,1}  =>  (p*B)*mask == p*(B*mask) bitwise (x*1 exact,
            // x*0 gives the same +/-0/NaN propagation). Safe to factor.
            const float Bm = __fmul_rn(B, mask);

            // dG = (p0*(1-G) - p1*S) * G
            const float dG = __fmul_rn(
                __fsub_rn(__fmul_rn(p0, __fsub_rn(1.0f, G)),
                          __fmul_rn(p1, S)),
                G);

            // dS = S * (p2*G - p3*(W + B*mask) - p4)
            const float dS = __fmul_rn(
                S,
                __fsub_rn(__fsub_rn(__fmul_rn(p2, G),
                                    __fmul_rn(p3, __fadd_rn(W, Bm))),
                          p4));

            // dW = W * (p5*S - p6*B*mask - p7) * W   (left-assoc: (W*(...))*W)
            const float dW = __fmul_rn(
                __fmul_rn(W,
                          __fsub_rn(__fsub_rn(__fmul_rn(p5, S),
                                              __fmul_rn(p6, Bm)),
                                    p7)),
                W);

            // dB = B*mask * (p8*(S+W) - p9)
            const float dB = __fmul_rn(
                Bm,
                __fsub_rn(__fmul_rn(p8, __fadd_rn(S, W)), p9));

            B = __fadd_rn(B, dB);
            W = __fadd_rn(W, dW);
            S = __fadd_rn(S, dS);
            G = __fadd_rn(G, dG);

            traj[j] = make_float4(B, W, S, G);
            jf = __fadd_rn(jf, 1.0f);
        }
    }

    __syncthreads();

    // Parallel fan-out: shared (num_steps x float4) -> global (num_steps x 5),
    // column 4 = i. Trivial vs. the serial loop (~160 KB of stores).
    const float iv = y0[4];
    for (int r = threadIdx.x; r < num_steps; r += blockDim.x) {
        const float4 s = traj[r];
        float* o = out + (size_t)r * 5;
        o[0] = s.x;
        o[1] = s.y;
        o[2] = s.z;
        o[3] = s.w;
        o[4] = iv;
    }
}

extern "C" void kernel_launch(void* const* d_in, const int* in_sizes, int n_in,
                              void* d_out, int out_size) {
    const float* y0     = (const float*)d_in[0];
    const float* params = (const float*)d_in[1];
    // num_steps is derivable from the output shape (num_steps, 5); avoids a
    // device->host read of d_in[2], keeping everything graph-capturable.
    const int num_steps = out_size / 5;

    const size_t smem = (size_t)num_steps * sizeof(float4);
    cudaFuncSetAttribute(bwsg_ode_kernel,
                         cudaFuncAttributeMaxDynamicSharedMemorySize,
                         (int)smem);
    bwsg_ode_kernel<<<1, 256, smem>>>(y0, params, (float*)d_out, num_steps);
}

// round 2
// speedup vs baseline: 1.4788x; 1.4788x over previous
#include <cuda_runtime.h>

// BWSGODE: 8192-step serial scalar ODE, latency-bound on a single thread.
//
// v2: FMA-contracted body (14 fp ops/iter) + mask phase-split.
//   mask = (1-fi) + fi*(j >= 4+i) is a step function of j: for integer j,
//   j >= thr  <=>  j >= ceilf(thr). So we run a short prologue with mask=0
//   (B frozen, B*mask = 0 exactly for finite operands) and a hot loop with
//   mask identically 1 (B*1 = B exactly), eliminating the mask product and
//   the float step counter from ~99.95% of iterations.
// State trajectory goes to shared via STS.128; the block then fans it out
// to the (num_steps, 5) global layout in parallel.

__global__ void __launch_bounds__(256, 1)
bwsg_ode_kernel(const float* __restrict__ y0,
                const float* __restrict__ p,
                float* __restrict__ out,
                int num_steps) {
    extern __shared__ float4 traj[];  // num_steps entries (128 KB @ 8192)

    if (threadIdx.x == 0) {
        float B = y0[0];
        float W = y0[1];
        float S = y0[2];
        float G = y0[3];
        const float iv = y0[4];

        const float p0 = p[0], p2 = p[2], p5 = p[5], p8 = p[8];
        const float np1 = -p[1], np3 = -p[3], np4 = -p[4];
        const float np6 = -p[6], np7 = -p[7], np9 = -p[9];
        const float np0 = -p0;

        // interventional flag and threshold, op-for-op with the reference
        const float fi  = (iv != 0.0f) ? 1.0f : 0.0f;
        const float thr = __fsub_rn(__fadd_rn(5.0f, iv), 1.0f);

        // First integer step index with mask==1.
        // Non-interventional: mask==1 from the start (j0 = 1).
        // Interventional: mask = (j >= thr); for integer j this is
        // j >= ceilf(thr) (fp compare of exact integers is exact).
        int j0 = 1;
        if (fi != 0.0f) {
            float ct = ceilf(thr);
            if (ct > 1.0f) {
                j0 = (ct >= (float)num_steps) ? num_steps : (int)ct;
            }
        }

        traj[0] = make_float4(B, W, S, G);

        // ---- Phase 1: mask == 0 (only when interventional), B frozen ----
        // dS = S*(p2*G - p3*W - p4); dW = W*(p5*S - p7)*W;
        // dG = (p0*(1-G) - p1*S)*G;  dB = 0.
        for (int j = 1; j < j0; ++j) {
            float a = __fmaf_rn(np0, G, p0);
            a       = __fmaf_rn(np1, S, a);
            float c = __fmaf_rn(p2, G, np4);
            float b = __fmaf_rn(np3, W, c);
            float d = __fmaf_rn(p5, S, np7);
            float e = __fmul_rn(W, d);
            float nS = __fmaf_rn(b, S, S);
            float nW = __fmaf_rn(e, W, W);
            float nG = __fmaf_rn(a, G, G);
            W = nW; S = nS; G = nG;
            traj[j] = make_float4(B, W, S, G);
        }

        // ---- Phase 2: mask == 1, hot loop (14 fp ops) ----
        #pragma unroll 8
        for (int j = j0; j < num_steps; ++j) {
            float a = __fmaf_rn(np0, G, p0);     // p0 - p0*G
            a       = __fmaf_rn(np1, S, a);      //   - p1*S
            float t = __fadd_rn(W, B);           // W + B
            float c = __fmaf_rn(p2, G, np4);     // p2*G - p4
            float b = __fmaf_rn(np3, t, c);      //   - p3*(W+B)
            float d = __fmaf_rn(p5, S, np7);     // p5*S - p7
            d       = __fmaf_rn(np6, B, d);      //   - p6*B
            float e = __fmul_rn(W, d);           // W*(...)
            float f = __fadd_rn(S, W);           // S + W
            float g = __fmaf_rn(p8, f, np9);     // p8*(S+W) - p9
            float nB = __fmaf_rn(g, B, B);       // B += dB
            float nW = __fmaf_rn(e, W, W);       // W += dW
            float nS = __fmaf_rn(b, S, S);       // S += dS
            float nG = __fmaf_rn(a, G, G);       // G += dG
            B = nB; W = nW; S = nS; G = nG;
            traj[j] = make_float4(B, W, S, G);
        }
    }

    __syncthreads();

    // Parallel fan-out: shared (num_steps x float4) -> global (num_steps x 5),
    // column 4 = i.
    const float iv = y0[4];
    for (int r = threadIdx.x; r < num_steps; r += blockDim.x) {
        const float4 s = traj[r];
        float* o = out + (size_t)r * 5;
        o[0] = s.x;
        o[1] = s.y;
        o[2] = s.z;
        o[3] = s.w;
        o[4] = iv;
    }
}

extern "C" void kernel_launch(void* const* d_in, const int* in_sizes, int n_in,
                              void* d_out, int out_size) {
    const float* y0     = (const float*)d_in[0];
    const float* params = (const float*)d_in[1];
    const int num_steps = out_size / 5;

    const size_t smem = (size_t)num_steps * sizeof(float4);
    cudaFuncSetAttribute(bwsg_ode_kernel,
                         cudaFuncAttributeMaxDynamicSharedMemorySize,
                         (int)smem);
    bwsg_ode_kernel<<<1, 256, smem>>>(y0, params, (float*)d_out, num_steps);
}